// round 15
// baseline (speedup 1.0000x reference)
#include <cuda_runtime.h>
#include <cuda_fp16.h>
#include <cstdint>

#define B 2048
#define T 128
#define C 192
#define H 96
#define NC 38
#define S 25
#define J3H 288        // 3*H
#define KX 230         // C + NC
#define GB 2           // batch items per fused step block

// ---------------- device scratch (no allocations allowed) ----------------
__device__ __half g_Hproj_h[(size_t)B * T * H];   // 50 MB fp16
__device__ __half g_in_h[(size_t)B * T * C];      // 100 MB fp16 copy of inputs
__device__ float g_h[B * H];
__device__ float g_hp[B * H];                     // h @ w_h2h^T + b_h2h, for NEXT att step
__device__ float g_WT_i2h[C * H];                 // [c][h]
__device__ float g_WT_h2h[H * H];                 // [k][h]
__device__ float g_WT_ih[KX * J3H];               // [k][j] fp32 (one-hot gather only)
__device__ __half2 g_WT_ih_h2[(C / 2 + 4) * J3H]; // [k2][j], pair over k, +4 rows prefetch pad
__device__ __half2 g_WT_hh_h2[(H / 2 + 4) * J3H]; // [k2][j], +4 rows prefetch pad
__device__ float g_WT_gen[H * NC];                // [h][nc]
__device__ int   g_is64;

// ---------------- packed fp32x2 helpers (Blackwell) ----------------
__device__ __forceinline__ unsigned long long pack2(float lo, float hi) {
    unsigned long long r;
    asm("mov.b64 %0, {%1, %2};" : "=l"(r) : "f"(lo), "f"(hi));
    return r;
}
__device__ __forceinline__ float2 unpack2(unsigned long long v) {
    float lo, hi;
    asm("mov.b64 {%0, %1}, %2;" : "=f"(lo), "=f"(hi) : "l"(v));
    return make_float2(lo, hi);
}
__device__ __forceinline__ void fmaX2(unsigned long long& d, unsigned long long a, unsigned long long b) {
    asm("fma.rn.f32x2 %0, %1, %2, %0;" : "+l"(d) : "l"(a), "l"(b));
}

// ---------------- fast math helpers ----------------
__device__ __forceinline__ __half2 tanh_h2(__half2 x) {   // att energy only: 2 tanh / 1 MUFU op
    unsigned xi = *reinterpret_cast<unsigned*>(&x);
    unsigned yi;
    asm("tanh.approx.f16x2 %0, %1;" : "=r"(yi) : "r"(xi));
    return *reinterpret_cast<__half2*>(&yi);
}
__device__ __forceinline__ float tanh_fast(float x) {     // GRU recurrence (precise path)
    x = fminf(fmaxf(x, -10.f), 10.f);
    float e = __expf(2.f * x);
    return __fdividef(e - 1.f, e + 1.f);
}
__device__ __forceinline__ float sigmoid_fast(float x) {
    return __fdividef(1.f, 1.f + __expf(-x));
}

// ---------------- prep: transposes + h/hp init + targets dtype probe ----------------
__global__ void prep_kernel(const float* __restrict__ w_i2h,
                            const float* __restrict__ w_h2h,
                            const float* __restrict__ b_h2h,
                            const float* __restrict__ w_ih,
                            const float* __restrict__ w_hh,
                            const float* __restrict__ w_gen,
                            const void*  __restrict__ targets_raw) {
    int i0 = blockIdx.x * blockDim.x + threadIdx.x;
    int stride = gridDim.x * blockDim.x;
    for (int i = i0; i < H * C; i += stride) { int h = i / C, c = i % C; g_WT_i2h[c * H + h] = w_i2h[i]; }
    for (int i = i0; i < H * H; i += stride) { int h = i / H, k = i % H; g_WT_h2h[k * H + h] = w_h2h[i]; }
    for (int i = i0; i < J3H * KX; i += stride) { int j = i / KX, k = i % KX; g_WT_ih[k * J3H + j] = w_ih[i]; }
    for (int i = i0; i < (C / 2) * J3H; i += stride) {
        int j = i % J3H, k2 = i / J3H;
        g_WT_ih_h2[k2 * J3H + j] = __floats2half2_rn(w_ih[j * KX + 2 * k2], w_ih[j * KX + 2 * k2 + 1]);
    }
    for (int i = i0; i < (H / 2) * J3H; i += stride) {
        int j = i % J3H, k2 = i / J3H;
        g_WT_hh_h2[k2 * J3H + j] = __floats2half2_rn(w_hh[j * H + 2 * k2], w_hh[j * H + 2 * k2 + 1]);
    }
    for (int i = i0; i < 4 * J3H; i += stride) {
        g_WT_ih_h2[(C / 2) * J3H + i] = __floats2half2_rn(0.f, 0.f);
        g_WT_hh_h2[(H / 2) * J3H + i] = __floats2half2_rn(0.f, 0.f);
    }
    for (int i = i0; i < NC * H; i += stride) { int n = i / H, h = i % H; g_WT_gen[h * NC + n] = w_gen[i]; }
    for (int i = i0; i < B * H; i += stride) { g_h[i] = 0.f; g_hp[i] = b_h2h[i % H]; }
    if (i0 == 0) {
        // Detect int64 vs int32 targets: valid int64 class indices are all in [0, NC).
        const long long* t64 = (const long long*)targets_raw;
        int ok = 1;
        for (int q = 0; q < 64; q++) {
            long long v = t64[q];
            if (v < 0 || v >= NC) { ok = 0; break; }
        }
        g_is64 = ok;
    }
}

// ---------------- Hproj = inputs @ w_i2h^T ([B*T, H], fp16 out) + fp16 inputs copy ----------------
#define HP_ROWS 64
#define HP_CK   64
__global__ void __launch_bounds__(256) hproj_kernel(const float* __restrict__ inputs) {
    __shared__ __align__(16) float in_sT[HP_CK][HP_ROWS];   // [cc][r] transposed tile
    __shared__ __align__(16) float wt_s[HP_CK][H];
    int tid = threadIdx.x;
    int tx = tid & 31, ty = tid >> 5;
    int rowbase = blockIdx.x * HP_ROWS;

    unsigned long long accp[4][3];
#pragma unroll
    for (int rp = 0; rp < 4; rp++)
#pragma unroll
        for (int k = 0; k < 3; k++) accp[rp][k] = pack2(0.f, 0.f);

    for (int c0 = 0; c0 < C; c0 += HP_CK) {
        const float4* wsrc = (const float4*)(g_WT_i2h + c0 * H);
        for (int idx = tid; idx < HP_CK * H / 4; idx += 256)
            ((float4*)wt_s)[idx] = wsrc[idx];
        for (int idx = tid; idx < HP_ROWS * HP_CK / 4; idx += 256) {
            int r = idx >> 4;
            int q = idx & 15;
            size_t gidx = (size_t)(rowbase + r) * C + c0 + q * 4;
            float4 v = *(const float4*)(inputs + gidx);
            in_sT[q * 4 + 0][r] = v.x;
            in_sT[q * 4 + 1][r] = v.y;
            in_sT[q * 4 + 2][r] = v.z;
            in_sT[q * 4 + 3][r] = v.w;
            ((__half2*)g_in_h)[gidx / 2]     = __floats2half2_rn(v.x, v.y);
            ((__half2*)g_in_h)[gidx / 2 + 1] = __floats2half2_rn(v.z, v.w);
        }
        __syncthreads();
#pragma unroll 2
        for (int cc = 0; cc < HP_CK; ++cc) {
            unsigned long long W0 = pack2(wt_s[cc][tx * 3 + 0], wt_s[cc][tx * 3 + 0]);
            unsigned long long W1 = pack2(wt_s[cc][tx * 3 + 1], wt_s[cc][tx * 3 + 1]);
            unsigned long long W2 = pack2(wt_s[cc][tx * 3 + 2], wt_s[cc][tx * 3 + 2]);
            const ulonglong2* ivp = (const ulonglong2*)&in_sT[cc][ty * 8];
            ulonglong2 iva = ivp[0], ivb = ivp[1];
            fmaX2(accp[0][0], iva.x, W0); fmaX2(accp[0][1], iva.x, W1); fmaX2(accp[0][2], iva.x, W2);
            fmaX2(accp[1][0], iva.y, W0); fmaX2(accp[1][1], iva.y, W1); fmaX2(accp[1][2], iva.y, W2);
            fmaX2(accp[2][0], ivb.x, W0); fmaX2(accp[2][1], ivb.x, W1); fmaX2(accp[2][2], ivb.x, W2);
            fmaX2(accp[3][0], ivb.y, W0); fmaX2(accp[3][1], ivb.y, W1); fmaX2(accp[3][2], ivb.y, W2);
        }
        __syncthreads();
    }
#pragma unroll
    for (int rp = 0; rp < 4; rp++) {
        float2 a0 = unpack2(accp[rp][0]);
        float2 a1 = unpack2(accp[rp][1]);
        float2 a2 = unpack2(accp[rp][2]);
        __half* d0 = g_Hproj_h + (size_t)(rowbase + ty * 8 + 2 * rp) * H + tx * 3;
        __half* d1 = d0 + H;
        d0[0] = __float2half_rn(a0.x); d0[1] = __float2half_rn(a1.x); d0[2] = __float2half_rn(a2.x);
        d1[0] = __float2half_rn(a0.y); d1[1] = __float2half_rn(a1.y); d1[2] = __float2half_rn(a2.y);
    }
}

// ---------------- fused per-step kernel: attention + GRU for 2 batch items ----------------
__global__ void __launch_bounds__(288, 7) step_kernel(const void* __restrict__ targets_raw,
                                                      const float* __restrict__ w_score,
                                                      const float* __restrict__ b_ih,
                                                      const float* __restrict__ b_hh,
                                                      const float* __restrict__ b_h2h,
                                                      const float* __restrict__ b_gen,
                                                      float* __restrict__ probs, int s) {
    __shared__ __half2 hp_h2[GB * (H / 2)];          // hp in half2 (phase A only)
    __shared__ float sv_s[H];
    __shared__ float epart[GB * T][9];               // 8 energy partials per (bb,t), pad to 9
    __shared__ float alpha_s[GB][T];
    __shared__ __align__(16) float xs2[C / 2][4];    // k-pair-packed context (filled locally!)
    __shared__ __align__(16) float hs2[H / 2][4];    // k-pair-packed h (then h_new)
    __shared__ float Ssum[GB][2 * H];
    __shared__ float INs[GB][H];
    __shared__ float HNs[GB][H];
    __shared__ int cls_s[GB];

    int tid = threadIdx.x;
    int w = tid >> 5, l = tid & 31;
    int b0 = blockIdx.x * GB;

    // ---- loads (hp->half2, sv, h, cls) ----
    if (tid < GB * (H / 2)) {
        int bb = tid / (H / 2), k2 = tid % (H / 2);
        hp_h2[tid] = __floats2half2_rn(g_hp[(b0 + bb) * H + 2 * k2],
                                       g_hp[(b0 + bb) * H + 2 * k2 + 1]);
    }
    if (tid < H) sv_s[tid] = w_score[tid];
    for (int idx = tid; idx < GB * H; idx += J3H) {
        int bb = idx / H, k = idx % H;
        hs2[k >> 1][(k & 1) * 2 + bb] = g_h[(b0 + bb) * H + k];
    }
    if (tid < GB) {
        int cls;
        if (g_is64) cls = (int)((const long long*)targets_raw)[(size_t)(b0 + tid) * S + s];
        else        cls = ((const int*)targets_raw)[(size_t)(b0 + tid) * S + s];
        cls_s[tid] = cls;
    }
    __syncthreads();

    // ---- phase A: energy partials with f16x2 tanh. 8 warps: bb=w>>2, t-range (w&3)*32..+32 ----
    if (w < 8) {
        int bb = w >> 2, tb = (w & 3) * 32;
        const __half2* hb2 = (const __half2*)(g_Hproj_h + (size_t)(b0 + bb) * T * H);
        const __half2* hph = hp_h2 + bb * (H / 2);
#pragma unroll 4
        for (int i = 0; i < 32; i++) {
            int t = tb + i;
            const __half2* row = hb2 + t * (H / 2);
            __half2 th0 = tanh_h2(__hadd2(row[l], hph[l]));
            float2 t0 = __half22float2(th0);
            float v = sv_s[2 * l] * t0.x + sv_s[2 * l + 1] * t0.y;
            if (l < 16) {
                __half2 th1 = tanh_h2(__hadd2(row[32 + l], hph[32 + l]));
                float2 t1 = __half22float2(th1);
                v += sv_s[64 + 2 * l] * t1.x + sv_s[65 + 2 * l] * t1.y;
            }
            v += __shfl_xor_sync(0xffffffffu, v, 16);
            v += __shfl_xor_sync(0xffffffffu, v, 8);
            if (l < 8) epart[bb * T + t][l] = v;
        }
    }
    __syncthreads();

    // ---- phase B: softmax, warp 0 -> b0, warp 1 -> b1 ----
    if (w < 2) {
        int bb = w;
        float e[4];
#pragma unroll
        for (int q = 0; q < 4; q++) {
            const float* ep = epart[bb * T + l + 32 * q];
            e[q] = ((ep[0] + ep[1]) + (ep[2] + ep[3])) + ((ep[4] + ep[5]) + (ep[6] + ep[7]));
        }
        float m = fmaxf(fmaxf(e[0], e[1]), fmaxf(e[2], e[3]));
#pragma unroll
        for (int off = 16; off > 0; off >>= 1) m = fmaxf(m, __shfl_xor_sync(0xffffffffu, m, off));
        float p0 = __expf(e[0] - m), p1 = __expf(e[1] - m), p2 = __expf(e[2] - m), p3 = __expf(e[3] - m);
        float ssum = p0 + p1 + p2 + p3;
#pragma unroll
        for (int off = 16; off > 0; off >>= 1) ssum += __shfl_xor_sync(0xffffffffu, ssum, off);
        float inv = __fdividef(1.f, ssum);
        alpha_s[bb][l]      = p0 * inv;
        alpha_s[bb][l + 32] = p1 * inv;
        alpha_s[bb][l + 64] = p2 * inv;
        alpha_s[bb][l + 96] = p3 * inv;
    }
    __syncthreads();

    // ---- phase C: context straight into xs2 (k-pair-packed), 192 threads ----
    if (tid < 192) {
        int bb = tid / 96, col = tid % 96;   // col = half2 column = k-pair index
        const __half2* ip = (const __half2*)g_in_h + (size_t)(b0 + bb) * T * 96 + col;
        float ax = 0.f, ay = 0.f;
#pragma unroll 8
        for (int t = 0; t < T; t++) {
            float2 f = __half22float2(ip[t * 96]);
            float al = alpha_s[bb][t];
            ax += al * f.x; ay += al * f.y;
        }
        xs2[col][bb]     = ax;   // k = 2*col   (even -> slot bb)
        xs2[col][2 + bb] = ay;   // k = 2*col+1 (odd  -> slot 2+bb)
    }
    __syncthreads();

    // ---- phase D: GRU GEMMs ----
    int j = tid;  // 0..287
    unsigned long long accI2 = pack2(b_ih[j] + g_WT_ih[(C + cls_s[0]) * J3H + j],
                                     b_ih[j] + g_WT_ih[(C + cls_s[1]) * J3H + j]);
    float bH = b_hh[j];
    unsigned long long accH2 = pack2(bH, bH);

    {
        const __half2* Wp = g_WT_ih_h2 + j;
        __half2 wv[4];
#pragma unroll
        for (int u = 0; u < 4; u++) wv[u] = Wp[u * J3H];
#pragma unroll 1
        for (int k2 = 0; k2 < C / 2; k2 += 4) {
            __half2 wn[4];
#pragma unroll
            for (int u = 0; u < 4; u++) wn[u] = Wp[(k2 + 4 + u) * J3H];  // pad rows keep in-bounds
#pragma unroll
            for (int u = 0; u < 4; u++) {
                float2 wf = __half22float2(wv[u]);
                ulonglong2 v = *(const ulonglong2*)&xs2[k2 + u][0];
                fmaX2(accI2, v.x, pack2(wf.x, wf.x));
                fmaX2(accI2, v.y, pack2(wf.y, wf.y));
            }
#pragma unroll
            for (int u = 0; u < 4; u++) wv[u] = wn[u];
        }
    }
    {
        const __half2* Wp = g_WT_hh_h2 + j;
        __half2 wv[4];
#pragma unroll
        for (int u = 0; u < 4; u++) wv[u] = Wp[u * J3H];
#pragma unroll 1
        for (int k2 = 0; k2 < H / 2; k2 += 4) {
            __half2 wn[4];
#pragma unroll
            for (int u = 0; u < 4; u++) wn[u] = Wp[(k2 + 4 + u) * J3H];
#pragma unroll
            for (int u = 0; u < 4; u++) {
                float2 wf = __half22float2(wv[u]);
                ulonglong2 v = *(const ulonglong2*)&hs2[k2 + u][0];
                fmaX2(accH2, v.x, pack2(wf.x, wf.x));
                fmaX2(accH2, v.y, pack2(wf.y, wf.y));
            }
#pragma unroll
            for (int u = 0; u < 4; u++) wv[u] = wn[u];
        }
    }

    {
        float2 iacc = unpack2(accI2);
        float2 hacc = unpack2(accH2);
        float accI[GB] = { iacc.x, iacc.y };
        float accH[GB] = { hacc.x, hacc.y };
        if (j < 2 * H) {
#pragma unroll
            for (int bb = 0; bb < GB; bb++) Ssum[bb][j] = accI[bb] + accH[bb];
        } else {
            int jj = j - 2 * H;
#pragma unroll
            for (int bb = 0; bb < GB; bb++) { INs[bb][jj] = accI[bb]; HNs[bb][jj] = accH[bb]; }
        }
    }
    __syncthreads();

    // gates + h update (GB*H = 192 threads)
    if (tid < GB * H) {
        int bb = tid / H, h = tid % H;
        float r = sigmoid_fast(Ssum[bb][h]);
        float z = sigmoid_fast(Ssum[bb][H + h]);
        float n = tanh_fast(INs[bb][h] + r * HNs[bb][h]);
        int slot = (h & 1) * 2 + bb;
        float hn = (1.f - z) * n + z * hs2[h >> 1][slot];
        g_h[(b0 + bb) * H + h] = hn;
        hs2[h >> 1][slot] = hn;   // own slot: read-then-write, race-free
    }
    __syncthreads();

    // generator: probs[b,s,:] = h_new @ w_gen^T + b_gen  (GB*NC = 76 threads)
    if (tid < GB * NC) {
        int bb = tid / NC, nc = tid % NC;
        float acc = b_gen[nc];
#pragma unroll 4
        for (int h = 0; h < H; h++) acc += g_WT_gen[h * NC + nc] * hs2[h >> 1][(h & 1) * 2 + bb];
        probs[(size_t)((b0 + bb) * S + s) * NC + nc] = acc;
    }

    // next-step hp: hp[b] = h_new @ w_h2h^T + b_h2h  (GB*H = 192 threads)
    if (tid < GB * H) {
        int bb = tid / H, h = tid % H;
        float acc = b_h2h[h];
#pragma unroll 4
        for (int k = 0; k < H; k++) acc += g_WT_h2h[k * H + h] * hs2[k >> 1][(k & 1) * 2 + bb];
        g_hp[(b0 + bb) * H + h] = acc;
    }
}

// ---------------- launch ----------------
extern "C" void kernel_launch(void* const* d_in, const int* in_sizes, int n_in,
                              void* d_out, int out_size) {
    const float* inputs  = (const float*)d_in[0];
    const void*  targets = d_in[1];
    const float* w_i2h   = (const float*)d_in[2];
    const float* w_h2h   = (const float*)d_in[3];
    const float* b_h2h   = (const float*)d_in[4];
    const float* w_score = (const float*)d_in[5];
    const float* w_ih    = (const float*)d_in[6];
    const float* w_hh    = (const float*)d_in[7];
    const float* b_ih    = (const float*)d_in[8];
    const float* b_hh    = (const float*)d_in[9];
    const float* w_gen   = (const float*)d_in[10];
    const float* b_gen   = (const float*)d_in[11];
    float* probs = (float*)d_out;

    prep_kernel<<<148, 256>>>(w_i2h, w_h2h, b_h2h, w_ih, w_hh, w_gen, targets);
    hproj_kernel<<<(B * T) / HP_ROWS, 256>>>(inputs);
    for (int s = 0; s < S; s++) {
        step_kernel<<<B / GB, J3H>>>(targets, w_score, b_ih, b_hh, b_h2h, b_gen, probs, s);
    }
}